// round 1
// baseline (speedup 1.0000x reference)
#include <cuda_runtime.h>
#include <math.h>

// Problem constants
#define BATCH   4
#define SEQ     2048
#define DMODEL  1024
#define DINNER  2048
#define DSTATE  64
#define MROWS   (BATCH*SEQ)      // 8192
#define CHUNK   128
#define NCHUNK  (SEQ/CHUNK)      // 16

// ---------------- scratch (device globals; no allocation allowed) ----------
__device__ float g_xi  [MROWS*DINNER];
__device__ float g_z   [MROWS*DINNER];
__device__ float g_Braw[MROWS*DSTATE];
__device__ float g_Craw[MROWS*DSTATE];
__device__ float g_a   [MROWS];
__device__ float g_P   [BATCH*NCHUNK];
__device__ float g_Bm  [MROWS*DINNER];
__device__ float g_Cm  [MROWS*DINNER];
__device__ float g_hfin [BATCH*NCHUNK*DINNER];
__device__ float g_carry[BATCH*NCHUNK*DINNER];
__device__ float g_y   [MROWS*DINNER];

// ---------------- 128x128x8 register-tiled SGEMM ---------------------------
// C[M,N] = A[M,K] @ B[K,N], all row-major fp32. Requires M%128==0, N%128==0,
// K%8==0, lda/ldb/ldc%4==0. SPLIT: columns [0,DINNER) -> C0, rest -> C1
// (both with leading dim ldc), used to peel xz into xi / z directly.
template<bool SPLIT>
__global__ void __launch_bounds__(256) sgemm128(
    const float* __restrict__ A, int lda,
    const float* __restrict__ B, int ldb,
    float* __restrict__ C0, float* __restrict__ C1, int ldc,
    int K)
{
    __shared__ float As[8][128];
    __shared__ float Bs[8][128];
    const int tid = threadIdx.x;
    const int m0  = blockIdx.y * 128;
    const int n0  = blockIdx.x * 128;

    const int arow = tid >> 1;             // 0..127
    const int acol = (tid & 1) << 2;       // 0 or 4
    const int brow = tid >> 5;             // 0..7
    const int bcol = (tid & 31) << 2;      // 0..124

    const int tx = tid & 15;
    const int ty = tid >> 4;

    float acc[8][8];
#pragma unroll
    for (int i = 0; i < 8; i++)
#pragma unroll
        for (int j = 0; j < 8; j++) acc[i][j] = 0.f;

    const float* Ap = A + (size_t)(m0 + arow) * lda;
    const float* Bp = B + n0 + bcol;

    for (int k0 = 0; k0 < K; k0 += 8) {
        float4 av = *(const float4*)(Ap + k0 + acol);
        float4 bv = *(const float4*)(Bp + (size_t)(k0 + brow) * ldb);
        __syncthreads();                 // previous tile's compute done
        As[acol + 0][arow] = av.x;
        As[acol + 1][arow] = av.y;
        As[acol + 2][arow] = av.z;
        As[acol + 3][arow] = av.w;
        *(float4*)(&Bs[brow][bcol]) = bv;
        __syncthreads();
#pragma unroll
        for (int k = 0; k < 8; k++) {
            float a[8], b[8];
            *(float4*)(a)     = *(const float4*)(&As[k][ty * 4]);
            *(float4*)(a + 4) = *(const float4*)(&As[k][64 + ty * 4]);
            *(float4*)(b)     = *(const float4*)(&Bs[k][tx * 4]);
            *(float4*)(b + 4) = *(const float4*)(&Bs[k][64 + tx * 4]);
#pragma unroll
            for (int i = 0; i < 8; i++)
#pragma unroll
                for (int j = 0; j < 8; j++)
                    acc[i][j] = fmaf(a[i], b[j], acc[i][j]);
        }
    }

#pragma unroll
    for (int ii = 0; ii < 2; ii++)
#pragma unroll
        for (int iu = 0; iu < 4; iu++) {
            int row = m0 + ii * 64 + ty * 4 + iu;
#pragma unroll
            for (int jj = 0; jj < 2; jj++) {
                int col = n0 + jj * 64 + tx * 4;
                float4 v = make_float4(acc[ii*4+iu][jj*4+0], acc[ii*4+iu][jj*4+1],
                                       acc[ii*4+iu][jj*4+2], acc[ii*4+iu][jj*4+3]);
                if (SPLIT) {
                    if (col < DINNER)
                        *(float4*)(C0 + (size_t)row * ldc + col) = v;
                    else
                        *(float4*)(C1 + (size_t)row * ldc + (col - DINNER)) = v;
                } else {
                    *(float4*)(C0 + (size_t)row * ldc + col) = v;
                }
            }
        }
}

// ---------------- GEMM2 (N=129) fused with softplus/exp epilogue ------------
// proj = xi @ W_xp; col 0 -> a = exp(-exp(A_log)*softplus(.)), cols 1..64 ->
// Braw, cols 65..128 -> Craw. One block = 16 rows, thread j = output column.
__global__ void __launch_bounds__(160) proj_kernel(
    const float* __restrict__ W_xp, const float* __restrict__ A_log)
{
    __shared__ float xs[16][64];
    const int tid = threadIdx.x;
    const int rb  = blockIdx.x * 16;
    float acc[16];
#pragma unroll
    for (int r = 0; r < 16; r++) acc[r] = 0.f;

    for (int k0 = 0; k0 < DINNER; k0 += 64) {
        __syncthreads();
        for (int i = tid; i < 16 * 64; i += 160) {
            int r = i >> 6, k = i & 63;
            xs[r][k] = g_xi[(size_t)(rb + r) * DINNER + k0 + k];
        }
        __syncthreads();
        if (tid < 129) {
#pragma unroll 16
            for (int k = 0; k < 64; k++) {
                float w = W_xp[(k0 + k) * 129 + tid];
#pragma unroll
                for (int r = 0; r < 16; r++) acc[r] = fmaf(xs[r][k], w, acc[r]);
            }
        }
    }

    if (tid == 0) {
        float Aneg = -expf(A_log[0]);
#pragma unroll
        for (int r = 0; r < 16; r++) {
            float x  = acc[r];
            float sp = fmaxf(x, 0.f) + log1pf(expf(-fabsf(x)));  // softplus
            g_a[rb + r] = expf(Aneg * sp);
        }
    } else if (tid < 65) {
        for (int r = 0; r < 16; r++)
            g_Braw[(size_t)(rb + r) * DSTATE + (tid - 1)] = acc[r];
    } else if (tid < 129) {
        for (int r = 0; r < 16; r++)
            g_Craw[(size_t)(rb + r) * DSTATE + (tid - 65)] = acc[r];
    }
}

// ---------------- chunk products of a ---------------------------------------
__global__ void chunkprod_kernel()
{
    int i = blockIdx.x * blockDim.x + threadIdx.x;   // (b*NCHUNK + c)
    if (i < BATCH * NCHUNK) {
        float p = 1.f;
        int base = i * CHUNK;
        for (int t = 0; t < CHUNK; t++) p *= g_a[base + t];
        g_P[i] = p;
    }
}

// ---------------- pass 1: local chunk scan -> chunk-final h -----------------
__global__ void __launch_bounds__(256) scan1_kernel()
{
    __shared__ float a_sm[CHUNK];
    int d = blockIdx.x * 256 + threadIdx.x;
    int c = blockIdx.y, b = blockIdx.z;
    int mbase = b * SEQ + c * CHUNK;
    if (threadIdx.x < CHUNK) a_sm[threadIdx.x] = g_a[mbase + threadIdx.x];
    __syncthreads();

    float h = 0.f;
    size_t off = (size_t)mbase * DINNER + d;
#pragma unroll 4
    for (int t = 0; t < CHUNK; t++) {
        size_t idx = off + (size_t)t * DINNER;
        h = fmaf(a_sm[t], h, g_Bm[idx] * g_xi[idx]);
    }
    g_hfin[(size_t)(b * NCHUNK + c) * DINNER + d] = h;
}

// ---------------- pass 2: carry across chunks (16 steps, tiny) --------------
__global__ void scan2_kernel()
{
    int gid = blockIdx.x * blockDim.x + threadIdx.x;  // 0..8191
    int b = gid / DINNER, d = gid % DINNER;
    float carry = 0.f;
    for (int c = 0; c < NCHUNK; c++) {
        int i = b * NCHUNK + c;
        g_carry[(size_t)i * DINNER + d] = carry;
        carry = g_P[i] * carry + g_hfin[(size_t)i * DINNER + d];
    }
}

// ---------------- pass 3: scan with carry, fused y = (C*h + D*xi)*silu(z) ---
__global__ void __launch_bounds__(256) scan3_kernel(const float* __restrict__ Dvec)
{
    __shared__ float a_sm[CHUNK];
    int d = blockIdx.x * 256 + threadIdx.x;
    int c = blockIdx.y, b = blockIdx.z;
    int mbase = b * SEQ + c * CHUNK;
    if (threadIdx.x < CHUNK) a_sm[threadIdx.x] = g_a[mbase + threadIdx.x];
    __syncthreads();

    float h  = g_carry[(size_t)(b * NCHUNK + c) * DINNER + d];
    float Dd = Dvec[d];
    size_t off = (size_t)mbase * DINNER + d;
#pragma unroll 2
    for (int t = 0; t < CHUNK; t++) {
        size_t idx = off + (size_t)t * DINNER;
        float xiv = g_xi[idx];
        h = fmaf(a_sm[t], h, g_Bm[idx] * xiv);
        float zv  = g_z[idx];
        float sil = zv / (1.f + expf(-zv));
        g_y[idx] = (g_Cm[idx] * h + Dd * xiv) * sil;
    }
}

// ---------------- launch -----------------------------------------------------
extern "C" void kernel_launch(void* const* d_in, const int* in_sizes, int n_in,
                              void* d_out, int out_size)
{
    const float* x     = (const float*)d_in[0];
    const float* W_in  = (const float*)d_in[1];
    const float* W_xp  = (const float*)d_in[2];
    const float* W_B   = (const float*)d_in[3];
    const float* W_C   = (const float*)d_in[4];
    const float* W_out = (const float*)d_in[5];
    const float* Dv    = (const float*)d_in[6];
    const float* A_log = (const float*)d_in[7];
    float* out = (float*)d_out;

    float *p_xi, *p_z, *p_Braw, *p_Craw, *p_Bm, *p_Cm, *p_y;
    cudaGetSymbolAddress((void**)&p_xi,   g_xi);
    cudaGetSymbolAddress((void**)&p_z,    g_z);
    cudaGetSymbolAddress((void**)&p_Braw, g_Braw);
    cudaGetSymbolAddress((void**)&p_Craw, g_Craw);
    cudaGetSymbolAddress((void**)&p_Bm,   g_Bm);
    cudaGetSymbolAddress((void**)&p_Cm,   g_Cm);
    cudaGetSymbolAddress((void**)&p_y,    g_y);

    // GEMM1: xz = x @ W_in, split into xi | z
    sgemm128<true><<<dim3((2 * DINNER) / 128, MROWS / 128), 256>>>(
        x, DMODEL, W_in, 2 * DINNER, p_xi, p_z, DINNER, DMODEL);

    // GEMM2 (N=129) + delta/a epilogue
    proj_kernel<<<MROWS / 16, 160>>>(W_xp, A_log);
    chunkprod_kernel<<<1, 64>>>();

    // GEMM3: B = Braw @ W_B ; C = Craw @ W_C
    sgemm128<false><<<dim3(DINNER / 128, MROWS / 128), 256>>>(
        p_Braw, DSTATE, W_B, DINNER, p_Bm, nullptr, DINNER, DSTATE);
    sgemm128<false><<<dim3(DINNER / 128, MROWS / 128), 256>>>(
        p_Craw, DSTATE, W_C, DINNER, p_Cm, nullptr, DINNER, DSTATE);

    // chunked scan
    scan1_kernel<<<dim3(DINNER / 256, NCHUNK, BATCH), 256>>>();
    scan2_kernel<<<MROWS / 256 / DINNER * DINNER ? 32 : 32, 256>>>();
    scan3_kernel<<<dim3(DINNER / 256, NCHUNK, BATCH), 256>>>(Dv);

    // GEMM4: out = y @ W_out
    sgemm128<false><<<dim3(DMODEL / 128, MROWS / 128), 256>>>(
        p_y, DINNER, W_out, DMODEL, out, nullptr, DMODEL, DINNER);
}

// round 5
// speedup vs baseline: 2.1832x; 2.1832x over previous
#include <cuda_runtime.h>
#include <math.h>

// Problem constants
#define BATCH   4
#define SEQ     2048
#define DMODEL  1024
#define DINNER  2048
#define DSTATE  64
#define MROWS   (BATCH*SEQ)      // 8192
#define CHUNK   128
#define NCHUNK  (SEQ/CHUNK)      // 16
#define NPROJ   256              // padded 129 -> 256

// ---------------- scratch (device globals; no allocation allowed) ----------
__device__ float g_xi  [MROWS*DINNER];
__device__ float g_z   [MROWS*DINNER];
__device__ float g_Braw[MROWS*DSTATE];
__device__ float g_Craw[MROWS*DSTATE];
__device__ float g_a   [MROWS];
__device__ float g_P   [BATCH*NCHUNK];
__device__ float g_Bm  [MROWS*DINNER];
__device__ float g_Cm  [MROWS*DINNER];
__device__ float g_hfin [BATCH*NCHUNK*DINNER];
__device__ float g_carry[BATCH*NCHUNK*DINNER];
__device__ float g_y   [MROWS*DINNER];
__device__ float g_proj[MROWS*NPROJ];
__device__ float g_Wxp_pad[DINNER*NPROJ];

// ---------------- TF32 tensor-core GEMM (mma.sync m16n8k8) ------------------
// C[M,N] = A[M,K] @ B[K,N], row-major fp32 in/out, TF32 compute, fp32 accum.
// M%128==0, N%128==0, K%16==0. SPLIT: cols [0,DINNER) -> C0, rest -> C1.
#define BM 128
#define BN 128
#define BKT 16
#define APAD 8
#define ASTR (BM + APAD)   // 136 -> conflict-free frag loads
#define BSTR (BN + APAD)

__device__ __forceinline__ float to_tf32(float x) {
    float y;
    asm("cvt.rna.tf32.f32 %0, %1;" : "=f"(y) : "f"(x));
    return y;
}

__device__ __forceinline__ void mma_tf32(
    float& c0, float& c1, float& c2, float& c3,
    unsigned a0, unsigned a1, unsigned a2, unsigned a3,
    unsigned b0, unsigned b1)
{
    asm volatile(
        "mma.sync.aligned.m16n8k8.row.col.f32.tf32.tf32.f32 "
        "{%0,%1,%2,%3}, {%4,%5,%6,%7}, {%8,%9}, {%0,%1,%2,%3};"
        : "+f"(c0), "+f"(c1), "+f"(c2), "+f"(c3)
        : "r"(a0), "r"(a1), "r"(a2), "r"(a3), "r"(b0), "r"(b1));
}

template<bool SPLIT>
__global__ void __launch_bounds__(256) tf32gemm(
    const float* __restrict__ A, int lda,
    const float* __restrict__ B, int ldb,
    float* __restrict__ C0, float* __restrict__ C1, int ldc,
    int K)
{
    __shared__ __align__(16) float As[2][BKT][ASTR];  // k-major
    __shared__ __align__(16) float Bs[2][BKT][BSTR];  // k-major (row = k)

    const int tid  = threadIdx.x;
    const int warp = tid >> 5;
    const int lane = tid & 31;
    const int lq   = lane & 3;       // k sub-index
    const int lr   = lane >> 2;      // 0..7
    const int wm   = (warp >> 2) * 64;
    const int wn   = (warp & 3) * 32;
    const int m0   = blockIdx.y * BM;
    const int n0   = blockIdx.x * BN;

    // staging indices
    const int am  = tid >> 1;            // A tile row 0..127
    const int ak  = (tid & 1) * 8;       // A k base (loads k ak..ak+7)
    const int bkr = tid >> 4;            // B tile k row 0..15
    const int bnc = (tid & 15) * 8;      // B col base (loads 8 cols)

    const float* Ap = A + (size_t)(m0 + am) * lda;
    const float* Bp = B + n0 + bnc;

    float acc[4][4][4];
#pragma unroll
    for (int i = 0; i < 4; i++)
#pragma unroll
        for (int j = 0; j < 4; j++)
#pragma unroll
            for (int c = 0; c < 4; c++) acc[i][j][c] = 0.f;

    // prefetch tile 0
    float4 ra0 = *(const float4*)(Ap + ak);
    float4 ra1 = *(const float4*)(Ap + ak + 4);
    float4 rb0 = *(const float4*)(Bp + (size_t)bkr * ldb);
    float4 rb1 = *(const float4*)(Bp + (size_t)bkr * ldb + 4);

    As[0][ak+0][am] = to_tf32(ra0.x); As[0][ak+1][am] = to_tf32(ra0.y);
    As[0][ak+2][am] = to_tf32(ra0.z); As[0][ak+3][am] = to_tf32(ra0.w);
    As[0][ak+4][am] = to_tf32(ra1.x); As[0][ak+5][am] = to_tf32(ra1.y);
    As[0][ak+6][am] = to_tf32(ra1.z); As[0][ak+7][am] = to_tf32(ra1.w);
    {
        float4 c0 = make_float4(to_tf32(rb0.x), to_tf32(rb0.y), to_tf32(rb0.z), to_tf32(rb0.w));
        float4 c1 = make_float4(to_tf32(rb1.x), to_tf32(rb1.y), to_tf32(rb1.z), to_tf32(rb1.w));
        *(float4*)(&Bs[0][bkr][bnc])     = c0;
        *(float4*)(&Bs[0][bkr][bnc + 4]) = c1;
    }
    __syncthreads();

    int cur = 0;
    for (int k0 = BKT; k0 <= K; k0 += BKT) {
        const bool more = (k0 < K);
        if (more) {
            ra0 = *(const float4*)(Ap + k0 + ak);
            ra1 = *(const float4*)(Ap + k0 + ak + 4);
            rb0 = *(const float4*)(Bp + (size_t)(k0 + bkr) * ldb);
            rb1 = *(const float4*)(Bp + (size_t)(k0 + bkr) * ldb + 4);
        }

        // compute on buffer 'cur'
#pragma unroll
        for (int ks = 0; ks < 2; ks++) {
            const int kb = ks * 8;
            unsigned af[4][4];
            unsigned bf[4][2];
#pragma unroll
            for (int mt = 0; mt < 4; mt++) {
                const int m = wm + mt * 16;
                af[mt][0] = __float_as_uint(As[cur][kb + lq    ][m + lr    ]);
                af[mt][1] = __float_as_uint(As[cur][kb + lq    ][m + 8 + lr]);
                af[mt][2] = __float_as_uint(As[cur][kb + 4 + lq][m + lr    ]);
                af[mt][3] = __float_as_uint(As[cur][kb + 4 + lq][m + 8 + lr]);
            }
#pragma unroll
            for (int nt = 0; nt < 4; nt++) {
                const int n = wn + nt * 8;
                bf[nt][0] = __float_as_uint(Bs[cur][kb + lq    ][n + lr]);
                bf[nt][1] = __float_as_uint(Bs[cur][kb + 4 + lq][n + lr]);
            }
#pragma unroll
            for (int mt = 0; mt < 4; mt++)
#pragma unroll
                for (int nt = 0; nt < 4; nt++)
                    mma_tf32(acc[mt][nt][0], acc[mt][nt][1], acc[mt][nt][2], acc[mt][nt][3],
                             af[mt][0], af[mt][1], af[mt][2], af[mt][3],
                             bf[nt][0], bf[nt][1]);
        }

        if (more) {
            const int nxt = cur ^ 1;
            As[nxt][ak+0][am] = to_tf32(ra0.x); As[nxt][ak+1][am] = to_tf32(ra0.y);
            As[nxt][ak+2][am] = to_tf32(ra0.z); As[nxt][ak+3][am] = to_tf32(ra0.w);
            As[nxt][ak+4][am] = to_tf32(ra1.x); As[nxt][ak+5][am] = to_tf32(ra1.y);
            As[nxt][ak+6][am] = to_tf32(ra1.z); As[nxt][ak+7][am] = to_tf32(ra1.w);
            float4 c0 = make_float4(to_tf32(rb0.x), to_tf32(rb0.y), to_tf32(rb0.z), to_tf32(rb0.w));
            float4 c1 = make_float4(to_tf32(rb1.x), to_tf32(rb1.y), to_tf32(rb1.z), to_tf32(rb1.w));
            *(float4*)(&Bs[nxt][bkr][bnc])     = c0;
            *(float4*)(&Bs[nxt][bkr][bnc + 4]) = c1;
        }
        __syncthreads();
        cur ^= 1;
    }

    // epilogue: c0 at (row, col), c1 (row, col+1), c2/c3 at row+8
#pragma unroll
    for (int mt = 0; mt < 4; mt++) {
#pragma unroll
        for (int nt = 0; nt < 4; nt++) {
            int row = m0 + wm + mt * 16 + lr;
            int col = n0 + wn + nt * 8 + lq * 2;
            float2 v0 = make_float2(acc[mt][nt][0], acc[mt][nt][1]);
            float2 v1 = make_float2(acc[mt][nt][2], acc[mt][nt][3]);
            if (SPLIT) {
                if (col < DINNER) {
                    *(float2*)(C0 + (size_t)row * ldc + col)       = v0;
                    *(float2*)(C0 + (size_t)(row + 8) * ldc + col) = v1;
                } else {
                    *(float2*)(C1 + (size_t)row * ldc + (col - DINNER))       = v0;
                    *(float2*)(C1 + (size_t)(row + 8) * ldc + (col - DINNER)) = v1;
                }
            } else {
                *(float2*)(C0 + (size_t)row * ldc + col)       = v0;
                *(float2*)(C0 + (size_t)(row + 8) * ldc + col) = v1;
            }
        }
    }
}

// ---------------- W_xp zero-pad to [DINNER, 256] -----------------------------
__global__ void pad_wxp_kernel(const float* __restrict__ W)
{
    int i = blockIdx.x * 256 + threadIdx.x;     // i < DINNER*NPROJ
    int k = i >> 8, j = i & 255;
    g_Wxp_pad[i] = (j < 129) ? W[k * 129 + j] : 0.f;
}

// ---------------- proj epilogue: a / Braw / Craw from padded proj -----------
__global__ void __launch_bounds__(128) proj_epi_kernel(const float* __restrict__ A_log)
{
    int row = blockIdx.x;
    int tid = threadIdx.x;
    const float* pr = g_proj + (size_t)row * NPROJ;
    if (tid < 64)
        g_Braw[(size_t)row * DSTATE + tid] = pr[1 + tid];
    else
        g_Craw[(size_t)row * DSTATE + (tid - 64)] = pr[65 + (tid - 64)];
    if (tid == 0) {
        float x  = pr[0];
        float sp = fmaxf(x, 0.f) + log1pf(expf(-fabsf(x)));  // softplus
        g_a[row] = expf(-expf(A_log[0]) * sp);
    }
}

// ---------------- chunk products of a ---------------------------------------
__global__ void chunkprod_kernel()
{
    int i = blockIdx.x * blockDim.x + threadIdx.x;   // (b*NCHUNK + c)
    if (i < BATCH * NCHUNK) {
        float p = 1.f;
        int base = i * CHUNK;
        for (int t = 0; t < CHUNK; t++) p *= g_a[base + t];
        g_P[i] = p;
    }
}

// ---------------- pass 1: local chunk scan -> chunk-final h -----------------
__global__ void __launch_bounds__(256) scan1_kernel()
{
    __shared__ float a_sm[CHUNK];
    int d = blockIdx.x * 256 + threadIdx.x;
    int c = blockIdx.y, b = blockIdx.z;
    int mbase = b * SEQ + c * CHUNK;
    if (threadIdx.x < CHUNK) a_sm[threadIdx.x] = g_a[mbase + threadIdx.x];
    __syncthreads();

    float h = 0.f;
    size_t off = (size_t)mbase * DINNER + d;
#pragma unroll 4
    for (int t = 0; t < CHUNK; t++) {
        size_t idx = off + (size_t)t * DINNER;
        h = fmaf(a_sm[t], h, g_Bm[idx] * g_xi[idx]);
    }
    g_hfin[(size_t)(b * NCHUNK + c) * DINNER + d] = h;
}

// ---------------- pass 2: carry across chunks (16 steps, tiny) --------------
__global__ void scan2_kernel()
{
    int gid = blockIdx.x * blockDim.x + threadIdx.x;  // 0..8191
    int b = gid / DINNER, d = gid % DINNER;
    float carry = 0.f;
    for (int c = 0; c < NCHUNK; c++) {
        int i = b * NCHUNK + c;
        g_carry[(size_t)i * DINNER + d] = carry;
        carry = g_P[i] * carry + g_hfin[(size_t)i * DINNER + d];
    }
}

// ---------------- pass 3: scan with carry, fused y = (C*h + D*xi)*silu(z) ---
__global__ void __launch_bounds__(256) scan3_kernel(const float* __restrict__ Dvec)
{
    __shared__ float a_sm[CHUNK];
    int d = blockIdx.x * 256 + threadIdx.x;
    int c = blockIdx.y, b = blockIdx.z;
    int mbase = b * SEQ + c * CHUNK;
    if (threadIdx.x < CHUNK) a_sm[threadIdx.x] = g_a[mbase + threadIdx.x];
    __syncthreads();

    float h  = g_carry[(size_t)(b * NCHUNK + c) * DINNER + d];
    float Dd = Dvec[d];
    size_t off = (size_t)mbase * DINNER + d;
#pragma unroll 2
    for (int t = 0; t < CHUNK; t++) {
        size_t idx = off + (size_t)t * DINNER;
        float xiv = g_xi[idx];
        h = fmaf(a_sm[t], h, g_Bm[idx] * xiv);
        float zv  = g_z[idx];
        float sil = zv / (1.f + expf(-zv));
        g_y[idx] = (g_Cm[idx] * h + Dd * xiv) * sil;
    }
}

// ---------------- launch -----------------------------------------------------
extern "C" void kernel_launch(void* const* d_in, const int* in_sizes, int n_in,
                              void* d_out, int out_size)
{
    const float* x     = (const float*)d_in[0];
    const float* W_in  = (const float*)d_in[1];
    const float* W_xp  = (const float*)d_in[2];
    const float* W_B   = (const float*)d_in[3];
    const float* W_C   = (const float*)d_in[4];
    const float* W_out = (const float*)d_in[5];
    const float* Dv    = (const float*)d_in[6];
    const float* A_log = (const float*)d_in[7];
    float* out = (float*)d_out;

    float *p_xi, *p_z, *p_Braw, *p_Craw, *p_Bm, *p_Cm, *p_y, *p_proj, *p_Wpad;
    cudaGetSymbolAddress((void**)&p_xi,   g_xi);
    cudaGetSymbolAddress((void**)&p_z,    g_z);
    cudaGetSymbolAddress((void**)&p_Braw, g_Braw);
    cudaGetSymbolAddress((void**)&p_Craw, g_Craw);
    cudaGetSymbolAddress((void**)&p_Bm,   g_Bm);
    cudaGetSymbolAddress((void**)&p_Cm,   g_Cm);
    cudaGetSymbolAddress((void**)&p_y,    g_y);
    cudaGetSymbolAddress((void**)&p_proj, g_proj);
    cudaGetSymbolAddress((void**)&p_Wpad, g_Wxp_pad);

    // GEMM1: xz = x @ W_in, split into xi | z   (M=8192, N=4096, K=1024)
    tf32gemm<true><<<dim3((2 * DINNER) / BN, MROWS / BM), 256>>>(
        x, DMODEL, W_in, 2 * DINNER, p_xi, p_z, DINNER, DMODEL);

    // GEMM2: proj = xi @ W_xp_pad  (N padded 129 -> 256)
    pad_wxp_kernel<<<(DINNER * NPROJ) / 256, 256>>>(W_xp);
    tf32gemm<false><<<dim3(NPROJ / BN, MROWS / BM), 256>>>(
        p_xi, DINNER, p_Wpad, NPROJ, p_proj, nullptr, NPROJ, DINNER);
    proj_epi_kernel<<<MROWS, 128>>>(A_log);
    chunkprod_kernel<<<1, 64>>>();

    // GEMM3: Bm = Braw @ W_B ; Cm = Craw @ W_C  (K=64)
    tf32gemm<false><<<dim3(DINNER / BN, MROWS / BM), 256>>>(
        p_Braw, DSTATE, W_B, DINNER, p_Bm, nullptr, DINNER, DSTATE);
    tf32gemm<false><<<dim3(DINNER / BN, MROWS / BM), 256>>>(
        p_Craw, DSTATE, W_C, DINNER, p_Cm, nullptr, DINNER, DSTATE);

    // chunked scan
    scan1_kernel<<<dim3(DINNER / 256, NCHUNK, BATCH), 256>>>();
    scan2_kernel<<<32, 256>>>();
    scan3_kernel<<<dim3(DINNER / 256, NCHUNK, BATCH), 256>>>(Dv);

    // GEMM4: out = y @ W_out  (M=8192, N=1024, K=2048)
    tf32gemm<false><<<dim3(DMODEL / BN, MROWS / BM), 256>>>(
        p_y, DINNER, W_out, DMODEL, out, nullptr, DMODEL, DINNER);
}

// round 6
// speedup vs baseline: 2.3807x; 1.0904x over previous
#include <cuda_runtime.h>
#include <math.h>
#include <stdint.h>

// Problem constants
#define BATCH   4
#define SEQ     2048
#define DMODEL  1024
#define DINNER  2048
#define DSTATE  64
#define MROWS   (BATCH*SEQ)      // 8192
#define CHUNK   128
#define NCHUNK  (SEQ/CHUNK)      // 16
#define NPROJ   256              // padded 129 -> 256

// ---------------- scratch (device globals; no allocation allowed) ----------
__device__ float g_xi  [MROWS*DINNER];   // full-precision xi (for scans)
__device__ float g_xir [MROWS*DINNER];   // tf32-rounded xi (GEMM2 operand)
__device__ float g_z   [MROWS*DINNER];
__device__ float g_Braw[MROWS*DSTATE];   // tf32-rounded at write
__device__ float g_Craw[MROWS*DSTATE];   // tf32-rounded at write
__device__ float g_a   [MROWS];
__device__ float g_P   [BATCH*NCHUNK];
__device__ float g_Bm  [MROWS*DINNER];
__device__ float g_Cm  [MROWS*DINNER];
__device__ float g_hfin [BATCH*NCHUNK*DINNER];
__device__ float g_carry[BATCH*NCHUNK*DINNER];
__device__ float g_y   [MROWS*DINNER];   // tf32-rounded at write
__device__ float g_proj[MROWS*NPROJ];
__device__ float g_Wxp_pad[DINNER*NPROJ];          // rounded + padded
__device__ float g_xr    [MROWS*DMODEL];           // rounded x
__device__ float g_Win_r [DMODEL*2*DINNER];        // rounded W_in
__device__ float g_Wout_r[DINNER*DMODEL];          // rounded W_out
__device__ float g_WB_r  [DSTATE*DINNER];          // rounded W_B
__device__ float g_WC_r  [DSTATE*DINNER];          // rounded W_C

// ---------------- helpers ----------------------------------------------------
__device__ __forceinline__ float to_tf32(float x) {
    float y;
    asm("cvt.rna.tf32.f32 %0, %1;" : "=f"(y) : "f"(x));
    return y;
}

__device__ __forceinline__ void cp_async16(uint32_t saddr, const void* gptr) {
    asm volatile("cp.async.cg.shared.global [%0], [%1], 16;" :: "r"(saddr), "l"(gptr));
}
__device__ __forceinline__ void cp_commit() {
    asm volatile("cp.async.commit_group;");
}
template<int N>
__device__ __forceinline__ void cp_wait() {
    asm volatile("cp.async.wait_group %0;" :: "n"(N));
}

__device__ __forceinline__ void mma_tf32(
    float& c0, float& c1, float& c2, float& c3,
    unsigned a0, unsigned a1, unsigned a2, unsigned a3,
    unsigned b0, unsigned b1)
{
    asm volatile(
        "mma.sync.aligned.m16n8k8.row.col.f32.tf32.tf32.f32 "
        "{%0,%1,%2,%3}, {%4,%5,%6,%7}, {%8,%9}, {%0,%1,%2,%3};"
        : "+f"(c0), "+f"(c1), "+f"(c2), "+f"(c3)
        : "r"(a0), "r"(a1), "r"(a2), "r"(a3), "r"(b0), "r"(b1));
}

// ---------------- elementwise tf32 rounding (float4) -------------------------
__global__ void round4_kernel(float* __restrict__ dst, const float* __restrict__ src)
{
    int i = (blockIdx.x * 256 + threadIdx.x) * 4;
    float4 v = *(const float4*)(src + i);
    v.x = to_tf32(v.x); v.y = to_tf32(v.y); v.z = to_tf32(v.z); v.w = to_tf32(v.w);
    *(float4*)(dst + i) = v;
}

// ---------------- W_xp: round + zero-pad to [DINNER, 256] --------------------
__global__ void pad_wxp_kernel(const float* __restrict__ W)
{
    int i = blockIdx.x * 256 + threadIdx.x;     // i < DINNER*NPROJ
    int k = i >> 8, j = i & 255;
    g_Wxp_pad[i] = (j < 129) ? to_tf32(W[k * 129 + j]) : 0.f;
}

// ---------------- TF32 tensor-core GEMM, cp.async 2-stage pipeline -----------
// C[M,N] = A[M,K] @ B[K,N], row-major. Operands must be pre-rounded to tf32.
// M%128==0, N%128==0, K%16==0, lda/ldb%4==0.
// SPLIT: cols [0,DINNER) -> C0 (+R0 = tf32-rounded copy), rest -> C1.
#define BM 128
#define BN 128
#define ASTRIDE 20     // 128 x (16+4): frag banks (20*lr+lq)%32 all distinct
#define BSTRIDE 136    // 16 x (128+8): frag banks (8*lq+lr) all distinct

template<bool SPLIT>
__global__ void __launch_bounds__(256) tf32gemm(
    const float* __restrict__ A, int lda,
    const float* __restrict__ B, int ldb,
    float* __restrict__ C0, float* __restrict__ C1, float* __restrict__ R0,
    int ldc, int K)
{
    __shared__ __align__(16) float As[2][BM][ASTRIDE];   // m-major
    __shared__ __align__(16) float Bs[2][16][BSTRIDE];   // k-major

    const int tid  = threadIdx.x;
    const int warp = tid >> 5;
    const int lane = tid & 31;
    const int lq   = lane & 3;
    const int lr   = lane >> 2;
    const int wm   = (warp >> 2) * 64;
    const int wn   = (warp & 3) * 32;
    const int m0   = blockIdx.y * BM;
    const int n0   = blockIdx.x * BN;

    // staging: A -> thread covers row am, k in [ak, ak+8)
    const int am  = tid >> 1;
    const int ak  = (tid & 1) * 8;
    // B -> thread covers k-row bkr, cols [bnc, bnc+8)
    const int bkr = tid >> 4;
    const int bnc = (tid & 15) * 8;

    const float* Ag = A + (size_t)(m0 + am) * lda + ak;
    const float* Bg = B + (size_t)bkr * ldb + n0 + bnc;

    uint32_t sA[2], sB[2];
    sA[0] = (uint32_t)__cvta_generic_to_shared(&As[0][am][ak]);
    sA[1] = (uint32_t)__cvta_generic_to_shared(&As[1][am][ak]);
    sB[0] = (uint32_t)__cvta_generic_to_shared(&Bs[0][bkr][bnc]);
    sB[1] = (uint32_t)__cvta_generic_to_shared(&Bs[1][bkr][bnc]);

    float acc[4][4][4];
#pragma unroll
    for (int i = 0; i < 4; i++)
#pragma unroll
        for (int j = 0; j < 4; j++)
#pragma unroll
            for (int c = 0; c < 4; c++) acc[i][j][c] = 0.f;

    // prologue: stage 0
    cp_async16(sA[0],      Ag);
    cp_async16(sA[0] + 16, Ag + 4);
    cp_async16(sB[0],      Bg);
    cp_async16(sB[0] + 16, Bg + 4);
    cp_commit();

    int cur = 0;
    for (int k0 = 0; k0 < K; k0 += 16) {
        const bool more = (k0 + 16) < K;
        if (more) {
            const int nxt = cur ^ 1;
            const float* Ag2 = Ag + (k0 + 16);
            const float* Bg2 = Bg + (size_t)(k0 + 16) * ldb;
            cp_async16(sA[nxt],      Ag2);
            cp_async16(sA[nxt] + 16, Ag2 + 4);
            cp_async16(sB[nxt],      Bg2);
            cp_async16(sB[nxt] + 16, Bg2 + 4);
            cp_commit();
            cp_wait<1>();
        } else {
            cp_wait<0>();
        }
        __syncthreads();

#pragma unroll
        for (int ks = 0; ks < 2; ks++) {
            const int kb = ks * 8;
            unsigned af[4][4];
            unsigned bf[4][2];
#pragma unroll
            for (int mt = 0; mt < 4; mt++) {
                const int m = wm + mt * 16;
                af[mt][0] = __float_as_uint(As[cur][m + lr    ][kb + lq    ]);
                af[mt][1] = __float_as_uint(As[cur][m + 8 + lr][kb + lq    ]);
                af[mt][2] = __float_as_uint(As[cur][m + lr    ][kb + 4 + lq]);
                af[mt][3] = __float_as_uint(As[cur][m + 8 + lr][kb + 4 + lq]);
            }
#pragma unroll
            for (int nt = 0; nt < 4; nt++) {
                const int n = wn + nt * 8;
                bf[nt][0] = __float_as_uint(Bs[cur][kb + lq    ][n + lr]);
                bf[nt][1] = __float_as_uint(Bs[cur][kb + 4 + lq][n + lr]);
            }
#pragma unroll
            for (int mt = 0; mt < 4; mt++)
#pragma unroll
                for (int nt = 0; nt < 4; nt++)
                    mma_tf32(acc[mt][nt][0], acc[mt][nt][1], acc[mt][nt][2], acc[mt][nt][3],
                             af[mt][0], af[mt][1], af[mt][2], af[mt][3],
                             bf[nt][0], bf[nt][1]);
        }
        __syncthreads();
        cur ^= 1;
    }

    // epilogue
#pragma unroll
    for (int mt = 0; mt < 4; mt++) {
#pragma unroll
        for (int nt = 0; nt < 4; nt++) {
            int row = m0 + wm + mt * 16 + lr;
            int col = n0 + wn + nt * 8 + lq * 2;
            float2 v0 = make_float2(acc[mt][nt][0], acc[mt][nt][1]);
            float2 v1 = make_float2(acc[mt][nt][2], acc[mt][nt][3]);
            if (SPLIT) {
                if (col < DINNER) {
                    *(float2*)(C0 + (size_t)row * ldc + col)       = v0;
                    *(float2*)(C0 + (size_t)(row + 8) * ldc + col) = v1;
                    float2 r0 = make_float2(to_tf32(v0.x), to_tf32(v0.y));
                    float2 r1 = make_float2(to_tf32(v1.x), to_tf32(v1.y));
                    *(float2*)(R0 + (size_t)row * ldc + col)       = r0;
                    *(float2*)(R0 + (size_t)(row + 8) * ldc + col) = r1;
                } else {
                    *(float2*)(C1 + (size_t)row * ldc + (col - DINNER))       = v0;
                    *(float2*)(C1 + (size_t)(row + 8) * ldc + (col - DINNER)) = v1;
                }
            } else {
                *(float2*)(C0 + (size_t)row * ldc + col)       = v0;
                *(float2*)(C0 + (size_t)(row + 8) * ldc + col) = v1;
            }
        }
    }
}

// ---------------- proj epilogue: a / Braw / Craw from padded proj -----------
__global__ void __launch_bounds__(128) proj_epi_kernel(const float* __restrict__ A_log)
{
    int row = blockIdx.x;
    int tid = threadIdx.x;
    const float* pr = g_proj + (size_t)row * NPROJ;
    if (tid < 64)
        g_Braw[(size_t)row * DSTATE + tid] = to_tf32(pr[1 + tid]);
    else
        g_Craw[(size_t)row * DSTATE + (tid - 64)] = to_tf32(pr[65 + (tid - 64)]);
    if (tid == 0) {
        float x  = pr[0];
        float sp = fmaxf(x, 0.f) + log1pf(expf(-fabsf(x)));  // softplus
        g_a[row] = expf(-expf(A_log[0]) * sp);
    }
}

// ---------------- chunk products of a ---------------------------------------
__global__ void chunkprod_kernel()
{
    int i = blockIdx.x * blockDim.x + threadIdx.x;   // (b*NCHUNK + c)
    if (i < BATCH * NCHUNK) {
        float p = 1.f;
        int base = i * CHUNK;
        for (int t = 0; t < CHUNK; t++) p *= g_a[base + t];
        g_P[i] = p;
    }
}

// ---------------- pass 1: local chunk scan -> chunk-final h -----------------
__global__ void __launch_bounds__(256) scan1_kernel()
{
    __shared__ float a_sm[CHUNK];
    int d = blockIdx.x * 256 + threadIdx.x;
    int c = blockIdx.y, b = blockIdx.z;
    int mbase = b * SEQ + c * CHUNK;
    if (threadIdx.x < CHUNK) a_sm[threadIdx.x] = g_a[mbase + threadIdx.x];
    __syncthreads();

    float h = 0.f;
    size_t off = (size_t)mbase * DINNER + d;
#pragma unroll 4
    for (int t = 0; t < CHUNK; t++) {
        size_t idx = off + (size_t)t * DINNER;
        h = fmaf(a_sm[t], h, g_Bm[idx] * g_xi[idx]);
    }
    g_hfin[(size_t)(b * NCHUNK + c) * DINNER + d] = h;
}

// ---------------- pass 2: carry across chunks (16 steps, tiny) --------------
__global__ void scan2_kernel()
{
    int gid = blockIdx.x * blockDim.x + threadIdx.x;  // 0..8191
    int b = gid / DINNER, d = gid % DINNER;
    float carry = 0.f;
    for (int c = 0; c < NCHUNK; c++) {
        int i = b * NCHUNK + c;
        g_carry[(size_t)i * DINNER + d] = carry;
        carry = g_P[i] * carry + g_hfin[(size_t)i * DINNER + d];
    }
}

// ---------------- pass 3: scan with carry, fused y = (C*h + D*xi)*silu(z) ---
// writes tf32-rounded y (GEMM4 operand)
__global__ void __launch_bounds__(256) scan3_kernel(const float* __restrict__ Dvec)
{
    __shared__ float a_sm[CHUNK];
    int d = blockIdx.x * 256 + threadIdx.x;
    int c = blockIdx.y, b = blockIdx.z;
    int mbase = b * SEQ + c * CHUNK;
    if (threadIdx.x < CHUNK) a_sm[threadIdx.x] = g_a[mbase + threadIdx.x];
    __syncthreads();

    float h  = g_carry[(size_t)(b * NCHUNK + c) * DINNER + d];
    float Dd = Dvec[d];
    size_t off = (size_t)mbase * DINNER + d;
#pragma unroll 2
    for (int t = 0; t < CHUNK; t++) {
        size_t idx = off + (size_t)t * DINNER;
        float xiv = g_xi[idx];
        h = fmaf(a_sm[t], h, g_Bm[idx] * xiv);
        float zv  = g_z[idx];
        float sil = zv / (1.f + expf(-zv));
        g_y[idx] = to_tf32((g_Cm[idx] * h + Dd * xiv) * sil);
    }
}

// ---------------- launch -----------------------------------------------------
extern "C" void kernel_launch(void* const* d_in, const int* in_sizes, int n_in,
                              void* d_out, int out_size)
{
    const float* x     = (const float*)d_in[0];
    const float* W_in  = (const float*)d_in[1];
    const float* W_xp  = (const float*)d_in[2];
    const float* W_B   = (const float*)d_in[3];
    const float* W_C   = (const float*)d_in[4];
    const float* W_out = (const float*)d_in[5];
    const float* Dv    = (const float*)d_in[6];
    const float* A_log = (const float*)d_in[7];
    float* out = (float*)d_out;

    float *p_xi, *p_xir, *p_z, *p_Braw, *p_Craw, *p_Bm, *p_Cm, *p_y, *p_proj;
    float *p_Wpad, *p_xr, *p_Win, *p_Wout, *p_WB, *p_WC;
    cudaGetSymbolAddress((void**)&p_xi,   g_xi);
    cudaGetSymbolAddress((void**)&p_xir,  g_xir);
    cudaGetSymbolAddress((void**)&p_z,    g_z);
    cudaGetSymbolAddress((void**)&p_Braw, g_Braw);
    cudaGetSymbolAddress((void**)&p_Craw, g_Craw);
    cudaGetSymbolAddress((void**)&p_Bm,   g_Bm);
    cudaGetSymbolAddress((void**)&p_Cm,   g_Cm);
    cudaGetSymbolAddress((void**)&p_y,    g_y);
    cudaGetSymbolAddress((void**)&p_proj, g_proj);
    cudaGetSymbolAddress((void**)&p_Wpad, g_Wxp_pad);
    cudaGetSymbolAddress((void**)&p_xr,   g_xr);
    cudaGetSymbolAddress((void**)&p_Win,  g_Win_r);
    cudaGetSymbolAddress((void**)&p_Wout, g_Wout_r);
    cudaGetSymbolAddress((void**)&p_WB,   g_WB_r);
    cudaGetSymbolAddress((void**)&p_WC,   g_WC_r);

    // 0) one-time tf32 rounding of all raw GEMM operands
    round4_kernel<<<(MROWS * DMODEL) / 1024, 256>>>(p_xr, x);
    round4_kernel<<<(DMODEL * 2 * DINNER) / 1024, 256>>>(p_Win, W_in);
    round4_kernel<<<(DINNER * DMODEL) / 1024, 256>>>(p_Wout, W_out);
    round4_kernel<<<(DSTATE * DINNER) / 1024, 256>>>(p_WB, W_B);
    round4_kernel<<<(DSTATE * DINNER) / 1024, 256>>>(p_WC, W_C);
    pad_wxp_kernel<<<(DINNER * NPROJ) / 256, 256>>>(W_xp);

    // GEMM1: xz = x @ W_in -> xi (full + rounded) | z   (8192x4096x1024)
    tf32gemm<true><<<dim3((2 * DINNER) / BN, MROWS / BM), 256>>>(
        p_xr, DMODEL, p_Win, 2 * DINNER, p_xi, p_z, p_xir, DINNER, DMODEL);

    // GEMM2: proj = xi_r @ W_xp_pad  (8192x256x2048)
    tf32gemm<false><<<dim3(NPROJ / BN, MROWS / BM), 256>>>(
        p_xir, DINNER, p_Wpad, NPROJ, p_proj, nullptr, nullptr, NPROJ, DINNER);
    proj_epi_kernel<<<MROWS, 128>>>(A_log);
    chunkprod_kernel<<<1, 64>>>();

    // GEMM3: Bm = Braw @ W_B ; Cm = Craw @ W_C  (8192x2048x64)
    tf32gemm<false><<<dim3(DINNER / BN, MROWS / BM), 256>>>(
        p_Braw, DSTATE, p_WB, DINNER, p_Bm, nullptr, nullptr, DINNER, DSTATE);
    tf32gemm<false><<<dim3(DINNER / BN, MROWS / BM), 256>>>(
        p_Craw, DSTATE, p_WC, DINNER, p_Cm, nullptr, nullptr, DINNER, DSTATE);

    // chunked scan
    scan1_kernel<<<dim3(DINNER / 256, NCHUNK, BATCH), 256>>>();
    scan2_kernel<<<32, 256>>>();
    scan3_kernel<<<dim3(DINNER / 256, NCHUNK, BATCH), 256>>>(Dv);

    // GEMM4: out = y @ W_out  (8192x1024x2048)
    tf32gemm<false><<<dim3(DMODEL / BN, MROWS / BM), 256>>>(
        p_y, DINNER, p_Wout, DMODEL, out, nullptr, nullptr, DMODEL, DINNER);
}

// round 8
// speedup vs baseline: 3.1370x; 1.3177x over previous
#include <cuda_runtime.h>
#include <math.h>
#include <stdint.h>

// Problem constants
#define BATCH   4
#define SEQ     2048
#define DMODEL  1024
#define DINNER  2048
#define DSTATE  64
#define MROWS   (BATCH*SEQ)      // 8192
#define CHUNK   128
#define NCHUNK  (SEQ/CHUNK)      // 16
#define NPROJ   256              // padded 129 -> 256

// ---------------- scratch (device globals; no allocation allowed) ----------
__device__ float g_xi  [MROWS*DINNER];    // full-precision xi (scans)
__device__ float g_z   [MROWS*DINNER];
__device__ float g_a   [MROWS];
__device__ float g_P   [BATCH*NCHUNK];
__device__ float g_Bm  [MROWS*DINNER];
__device__ float g_Cm  [MROWS*DINNER];
__device__ float g_hfin [BATCH*NCHUNK*DINNER];
__device__ float g_carry[BATCH*NCHUNK*DINNER];
__device__ float g_proj[MROWS*NPROJ];
// fragment-major (perm) operands
__device__ float g_xAP  [MROWS*DMODEL];    // x, A-perm, K=1024
__device__ float g_xirP [MROWS*DINNER];    // xi rounded, A-perm, K=2048
__device__ float g_BrawP[MROWS*DSTATE];    // A-perm, K=64
__device__ float g_CrawP[MROWS*DSTATE];    // A-perm, K=64
__device__ float g_yP   [MROWS*DINNER];    // y rounded, A-perm, K=2048
__device__ float g_WinB [DMODEL*2*DINNER]; // B-perm [K=1024][N=4096]
__device__ float g_WxpB [DINNER*NPROJ];    // B-perm [K=2048][N=256] (padded)
__device__ float g_WBB  [DSTATE*DINNER];   // B-perm [K=64][N=2048]
__device__ float g_WCB  [DSTATE*DINNER];   // B-perm [K=64][N=2048]
__device__ float g_WoutB[DINNER*DMODEL];   // B-perm [K=2048][N=1024]

// ---------------- helpers ----------------------------------------------------
__device__ __forceinline__ float to_tf32(float x) {
    float y;
    asm("cvt.rna.tf32.f32 %0, %1;" : "=f"(y) : "f"(x));
    return y;
}
__device__ __forceinline__ void cp_async16(uint32_t saddr, const void* gptr) {
    asm volatile("cp.async.cg.shared.global [%0], [%1], 16;" :: "r"(saddr), "l"(gptr));
}
__device__ __forceinline__ void cp_commit() {
    asm volatile("cp.async.commit_group;");
}
template<int N>
__device__ __forceinline__ void cp_wait() {
    asm volatile("cp.async.wait_group %0;" :: "n"(N));
}
__device__ __forceinline__ void mma_tf32(
    float& c0, float& c1, float& c2, float& c3,
    unsigned a0, unsigned a1, unsigned a2, unsigned a3,
    unsigned b0, unsigned b1)
{
    asm volatile(
        "mma.sync.aligned.m16n8k8.row.col.f32.tf32.tf32.f32 "
        "{%0,%1,%2,%3}, {%4,%5,%6,%7}, {%8,%9}, {%0,%1,%2,%3};"
        : "+f"(c0), "+f"(c1), "+f"(c2), "+f"(c3)
        : "r"(a0), "r"(a1), "r"(a2), "r"(a3), "r"(b0), "r"(b1));
}

// fragment-major index helpers.
// A frag (m16n8k8): lane = (m%8)*4 + (k%4); slot = ((m%16)>=8) + 2*((k%8)>=4)
__device__ __forceinline__ size_t permA_idx(int m, int k, int K8) {
    return ((size_t)((m >> 4) * K8 + (k >> 3))) * 128
         + (((m & 7) * 4 + (k & 3)) << 2) + ((m >> 3) & 1) + 2 * ((k >> 2) & 1);
}
// B frag: lane = (n%8)*4 + (k%4); slot = ((k%8)>=4)
__device__ __forceinline__ size_t permB_idx(int k, int n, int K8) {
    return ((size_t)((n >> 3) * K8 + (k >> 3))) * 64
         + (((n & 7) * 4 + (k & 3)) << 1) + ((k >> 2) & 1);
}

// ---------------- operand prep kernels ---------------------------------------
__global__ void permA_round_kernel(float* __restrict__ dst,
                                   const float* __restrict__ src, int K)
{
    int idx = blockIdx.x * 256 + threadIdx.x;
    int m = idx / K, k = idx % K;
    dst[permA_idx(m, k, K >> 3)] = to_tf32(src[idx]);
}

__global__ void permB_round_kernel(float* __restrict__ dst,
                                   const float* __restrict__ src,
                                   int K, int N, int ldsrc, int ncols)
{
    int idx = blockIdx.x * 256 + threadIdx.x;   // K*N total
    int k = idx / N, n = idx % N;
    float v = (n < ncols) ? to_tf32(src[(size_t)k * ldsrc + n]) : 0.f;
    dst[permB_idx(k, n, K >> 3)] = v;
}

// ---------------- TF32 mma.sync GEMM, frag-major smem, 3-stage cp.async ------
// C[M,N] = A@B. A in A-perm layout (K8=K/8), B in B-perm layout.
// CTA 128x128, BK=16, 8 warps (2m x 4n), warp tile 64x32.
// MODE 0: plain C0[ldc]. MODE 1 (GEMM1): col<DINNER -> xi(C0)+xirP(P0, rounded,
// perm K8=256); else z(C1).
#define STG_FLOATS 4096          // 16KB per stage (A 8KB + B 8KB)

template<int MODE>
__global__ void __launch_bounds__(256) tcmma_gemm(
    const float* __restrict__ Ap, const float* __restrict__ Bp,
    float* __restrict__ C0, float* __restrict__ C1, float* __restrict__ P0,
    int ldc, int K)
{
    __shared__ __align__(16) float sm[3 * STG_FLOATS];   // 48KB

    const int tid  = threadIdx.x;
    const int warp = tid >> 5;
    const int lane = tid & 31;
    const int lq   = lane & 3;
    const int lr   = lane >> 2;
    const int m0   = blockIdx.y * 128;
    const int n0   = blockIdx.x * 128;
    const int K8   = K >> 3;
    const int niter = K >> 4;
    const int wmg  = (warp >> 2) * 4;   // warp m16-group base (0 / 4)
    const int wng  = (warp & 3) * 4;    // warp n8-group base (0,4,8,12)

    const uint32_t sbase = (uint32_t)__cvta_generic_to_shared(sm);

    float acc[4][4][4];
#pragma unroll
    for (int i = 0; i < 4; i++)
#pragma unroll
        for (int j = 0; j < 4; j++)
#pragma unroll
            for (int c = 0; c < 4; c++) acc[i][j][c] = 0.f;

    // stage loader: K16-chunk i into buffer s
    auto stage = [&](int i, int s) {
#pragma unroll
        for (int rep = 0; rep < 2; rep++) {
            int c = tid + rep * 256;          // 512 A chunks of 16B
            int mgl = c >> 6, kgl = (c >> 5) & 1, ln = c & 31;
            cp_async16(sbase + s * 16384 + c * 16,
                Ap + ((size_t)((m0 >> 4) + mgl) * K8 + (i * 2 + kgl)) * 128 + ln * 4);
        }
#pragma unroll
        for (int rep = 0; rep < 2; rep++) {
            int c = tid + rep * 256;          // 512 B chunks of 16B
            int ngl = c >> 5, kgl = (c >> 4) & 1, lp = c & 15;
            cp_async16(sbase + s * 16384 + 8192 + c * 16,
                Bp + ((size_t)((n0 >> 3) + ngl) * K8 + (i * 2 + kgl)) * 64 + lp * 4);
        }
    };

    stage(0, 0); cp_commit();
    stage(1, 1); cp_commit();

    for (int i = 0; i < niter; i++) {
        if (i == niter - 1) cp_wait<0>(); else cp_wait<1>();
        __syncthreads();
        if (i + 2 < niter) { stage(i + 2, (i + 2) % 3); cp_commit(); }

        const float* sa = sm + (i % 3) * STG_FLOATS;
        const float* sb = sa + 2048;
#pragma unroll
        for (int ks = 0; ks < 2; ks++) {
            float4 afv[4];
            float2 bfv[4];
#pragma unroll
            for (int mt = 0; mt < 4; mt++)
                afv[mt] = *(const float4*)(sa + ((wmg + mt) * 2 + ks) * 128 + lane * 4);
#pragma unroll
            for (int nt = 0; nt < 4; nt++)
                bfv[nt] = *(const float2*)(sb + ((wng + nt) * 2 + ks) * 64 + lane * 2);
#pragma unroll
            for (int mt = 0; mt < 4; mt++)
#pragma unroll
                for (int nt = 0; nt < 4; nt++)
                    mma_tf32(acc[mt][nt][0], acc[mt][nt][1], acc[mt][nt][2], acc[mt][nt][3],
                             __float_as_uint(afv[mt].x), __float_as_uint(afv[mt].y),
                             __float_as_uint(afv[mt].z), __float_as_uint(afv[mt].w),
                             __float_as_uint(bfv[nt].x), __float_as_uint(bfv[nt].y));
        }
    }

    // epilogue
#pragma unroll
    for (int mt = 0; mt < 4; mt++) {
#pragma unroll
        for (int nt = 0; nt < 4; nt++) {
            int row = m0 + (warp >> 2) * 64 + mt * 16 + lr;
            int col = n0 + (warp & 3) * 32 + nt * 8 + lq * 2;
            float2 v0 = make_float2(acc[mt][nt][0], acc[mt][nt][1]);
            float2 v1 = make_float2(acc[mt][nt][2], acc[mt][nt][3]);
            if (MODE == 1) {
                if (col < DINNER) {
                    *(float2*)(C0 + (size_t)row * DINNER + col)       = v0;
                    *(float2*)(C0 + (size_t)(row + 8) * DINNER + col) = v1;
                    P0[permA_idx(row,     col,     256)] = to_tf32(v0.x);
                    P0[permA_idx(row,     col + 1, 256)] = to_tf32(v0.y);
                    P0[permA_idx(row + 8, col,     256)] = to_tf32(v1.x);
                    P0[permA_idx(row + 8, col + 1, 256)] = to_tf32(v1.y);
                } else {
                    *(float2*)(C1 + (size_t)row * DINNER + col - DINNER)       = v0;
                    *(float2*)(C1 + (size_t)(row + 8) * DINNER + col - DINNER) = v1;
                }
            } else {
                *(float2*)(C0 + (size_t)row * ldc + col)       = v0;
                *(float2*)(C0 + (size_t)(row + 8) * ldc + col) = v1;
            }
        }
    }
}

// ---------------- proj epilogue: a / BrawP / CrawP from padded proj ----------
__global__ void __launch_bounds__(128) proj_epi_kernel(const float* __restrict__ A_log)
{
    int row = blockIdx.x;
    int tid = threadIdx.x;
    const float* pr = g_proj + (size_t)row * NPROJ;
    if (tid < 64)
        g_BrawP[permA_idx(row, tid, 8)] = to_tf32(pr[1 + tid]);
    else
        g_CrawP[permA_idx(row, tid - 64, 8)] = to_tf32(pr[65 + (tid - 64)]);
    if (tid == 0) {
        float x  = pr[0];
        float sp = fmaxf(x, 0.f) + log1pf(expf(-fabsf(x)));  // softplus
        g_a[row] = expf(-expf(A_log[0]) * sp);
    }
}

// ---------------- chunk products of a ---------------------------------------
__global__ void chunkprod_kernel()
{
    int i = blockIdx.x * blockDim.x + threadIdx.x;
    if (i < BATCH * NCHUNK) {
        float p = 1.f;
        int base = i * CHUNK;
        for (int t = 0; t < CHUNK; t++) p *= g_a[base + t];
        g_P[i] = p;
    }
}

// ---------------- pass 1: local chunk scan -> chunk-final h -----------------
__global__ void __launch_bounds__(256) scan1_kernel()
{
    __shared__ float a_sm[CHUNK];
    int d = blockIdx.x * 256 + threadIdx.x;
    int c = blockIdx.y, b = blockIdx.z;
    int mbase = b * SEQ + c * CHUNK;
    if (threadIdx.x < CHUNK) a_sm[threadIdx.x] = g_a[mbase + threadIdx.x];
    __syncthreads();

    float h = 0.f;
    size_t off = (size_t)mbase * DINNER + d;
#pragma unroll 4
    for (int t = 0; t < CHUNK; t++) {
        size_t idx = off + (size_t)t * DINNER;
        h = fmaf(a_sm[t], h, g_Bm[idx] * g_xi[idx]);
    }
    g_hfin[(size_t)(b * NCHUNK + c) * DINNER + d] = h;
}

// ---------------- pass 2: carry across chunks --------------------------------
__global__ void scan2_kernel()
{
    int gid = blockIdx.x * blockDim.x + threadIdx.x;
    int b = gid / DINNER, d = gid % DINNER;
    float carry = 0.f;
    for (int c = 0; c < NCHUNK; c++) {
        int i = b * NCHUNK + c;
        g_carry[(size_t)i * DINNER + d] = carry;
        carry = g_P[i] * carry + g_hfin[(size_t)i * DINNER + d];
    }
}

// ---------------- pass 3: scan + fused y = (C*h + D*xi)*silu(z) --------------
// writes tf32-rounded y directly in A-perm layout (GEMM4 operand, K8=256)
__global__ void __launch_bounds__(256) scan3_kernel(const float* __restrict__ Dvec)
{
    __shared__ float a_sm[CHUNK];
    int d = blockIdx.x * 256 + threadIdx.x;
    int c = blockIdx.y, b = blockIdx.z;
    int mbase = b * SEQ + c * CHUNK;
    if (threadIdx.x < CHUNK) a_sm[threadIdx.x] = g_a[mbase + threadIdx.x];
    __syncthreads();

    float h  = g_carry[(size_t)(b * NCHUNK + c) * DINNER + d];
    float Dd = Dvec[d];
    size_t off = (size_t)mbase * DINNER + d;
#pragma unroll 2
    for (int t = 0; t < CHUNK; t++) {
        size_t idx = off + (size_t)t * DINNER;
        float xiv = g_xi[idx];
        h = fmaf(a_sm[t], h, g_Bm[idx] * xiv);
        float zv  = g_z[idx];
        float sil = zv / (1.f + expf(-zv));
        g_yP[permA_idx(mbase + t, d, 256)] = to_tf32((g_Cm[idx] * h + Dd * xiv) * sil);
    }
}

// ---------------- launch -----------------------------------------------------
extern "C" void kernel_launch(void* const* d_in, const int* in_sizes, int n_in,
                              void* d_out, int out_size)
{
    const float* x     = (const float*)d_in[0];
    const float* W_in  = (const float*)d_in[1];
    const float* W_xp  = (const float*)d_in[2];
    const float* W_B   = (const float*)d_in[3];
    const float* W_C   = (const float*)d_in[4];
    const float* W_out = (const float*)d_in[5];
    const float* Dv    = (const float*)d_in[6];
    const float* A_log = (const float*)d_in[7];
    float* out = (float*)d_out;

    float *p_xi, *p_z, *p_Bm, *p_Cm, *p_proj;
    float *p_xAP, *p_xirP, *p_BrawP, *p_CrawP, *p_yP;
    float *p_WinB, *p_WxpB, *p_WBB, *p_WCB, *p_WoutB;
    cudaGetSymbolAddress((void**)&p_xi,    g_xi);
    cudaGetSymbolAddress((void**)&p_z,     g_z);
    cudaGetSymbolAddress((void**)&p_Bm,    g_Bm);
    cudaGetSymbolAddress((void**)&p_Cm,    g_Cm);
    cudaGetSymbolAddress((void**)&p_proj,  g_proj);
    cudaGetSymbolAddress((void**)&p_xAP,   g_xAP);
    cudaGetSymbolAddress((void**)&p_xirP,  g_xirP);
    cudaGetSymbolAddress((void**)&p_BrawP, g_BrawP);
    cudaGetSymbolAddress((void**)&p_CrawP, g_CrawP);
    cudaGetSymbolAddress((void**)&p_yP,    g_yP);
    cudaGetSymbolAddress((void**)&p_WinB,  g_WinB);
    cudaGetSymbolAddress((void**)&p_WxpB,  g_WxpB);
    cudaGetSymbolAddress((void**)&p_WBB,   g_WBB);
    cudaGetSymbolAddress((void**)&p_WCB,   g_WCB);
    cudaGetSymbolAddress((void**)&p_WoutB, g_WoutB);

    // 0) operand prep (round once, write fragment-major layouts)
    permA_round_kernel<<<(MROWS * DMODEL) / 256, 256>>>(p_xAP, x, DMODEL);
    permB_round_kernel<<<(DMODEL * 2 * DINNER) / 256, 256>>>(
        p_WinB, W_in, DMODEL, 2 * DINNER, 2 * DINNER, 2 * DINNER);
    permB_round_kernel<<<(DINNER * NPROJ) / 256, 256>>>(
        p_WxpB, W_xp, DINNER, NPROJ, 129, 129);
    permB_round_kernel<<<(DSTATE * DINNER) / 256, 256>>>(
        p_WBB, W_B, DSTATE, DINNER, DINNER, DINNER);
    permB_round_kernel<<<(DSTATE * DINNER) / 256, 256>>>(
        p_WCB, W_C, DSTATE, DINNER, DINNER, DINNER);
    permB_round_kernel<<<(DINNER * DMODEL) / 256, 256>>>(
        p_WoutB, W_out, DINNER, DMODEL, DMODEL, DMODEL);

    // GEMM1: xz = x @ W_in -> xi | z (+ xir perm)   (8192 x 4096 x 1024)
    tcmma_gemm<1><<<dim3((2 * DINNER) / 128, MROWS / 128), 256>>>(
        p_xAP, p_WinB, p_xi, p_z, p_xirP, DINNER, DMODEL);

    // GEMM2: proj = xi_r @ W_xp_pad   (8192 x 256 x 2048)
    tcmma_gemm<0><<<dim3(NPROJ / 128, MROWS / 128), 256>>>(
        p_xirP, p_WxpB, p_proj, nullptr, nullptr, NPROJ, DINNER);
    proj_epi_kernel<<<MROWS, 128>>>(A_log);
    chunkprod_kernel<<<1, 64>>>();

    // GEMM3: Bm = Braw @ W_B ; Cm = Craw @ W_C   (8192 x 2048 x 64)
    tcmma_gemm<0><<<dim3(DINNER / 128, MROWS / 128), 256>>>(
        p_BrawP, p_WBB, p_Bm, nullptr, nullptr, DINNER, DSTATE);
    tcmma_gemm<0><<<dim3(DINNER / 128, MROWS / 128), 256>>>(
        p_CrawP, p_WCB, p_Cm, nullptr, nullptr, DINNER, DSTATE);

    // chunked scan
    scan1_kernel<<<dim3(DINNER / 256, NCHUNK, BATCH), 256>>>();
    scan2_kernel<<<32, 256>>>();
    scan3_kernel<<<dim3(DINNER / 256, NCHUNK, BATCH), 256>>>(Dv);

    // GEMM4: out = y @ W_out   (8192 x 1024 x 2048)
    tcmma_gemm<0><<<dim3(DMODEL / 128, MROWS / 128), 256>>>(
        p_yP, p_WoutB, out, nullptr, nullptr, DMODEL, DINNER);
}

// round 9
// speedup vs baseline: 4.4519x; 1.4192x over previous
#include <cuda_runtime.h>
#include <cuda_fp16.h>
#include <math.h>
#include <stdint.h>

// Problem constants
#define BATCH   4
#define SEQ     2048
#define DMODEL  1024
#define DINNER  2048
#define DSTATE  64
#define MROWS   (BATCH*SEQ)      // 8192
#define CHUNK   128
#define NCHUNK  (SEQ/CHUNK)      // 16
#define NPROJ   256              // padded 129 -> 256

// ---------------- scratch (device globals; no allocation allowed) ----------
__device__ float g_xi  [MROWS*DINNER];    // full-precision xi (scans)
__device__ float g_z   [MROWS*DINNER];
__device__ float g_a   [MROWS];
__device__ float g_P   [BATCH*NCHUNK];
__device__ float g_Bm  [MROWS*DINNER];
__device__ float g_Cm  [MROWS*DINNER];
__device__ float g_hfin [BATCH*NCHUNK*DINNER];
__device__ float g_carry[BATCH*NCHUNK*DINNER];
__device__ float g_proj[MROWS*NPROJ];
// fragment-major (perm) fp16 operands
__device__ __half g_xAP  [MROWS*DMODEL];    // x, A-perm, K=1024
__device__ __half g_xirP [MROWS*DINNER];    // xi rounded, A-perm, K=2048
__device__ __half g_BrawP[MROWS*DSTATE];    // A-perm, K=64
__device__ __half g_CrawP[MROWS*DSTATE];    // A-perm, K=64
__device__ __half g_yP   [MROWS*DINNER];    // y rounded, A-perm, K=2048
__device__ __half g_WinB [DMODEL*2*DINNER]; // B-perm [K=1024][N=4096]
__device__ __half g_WxpB [DINNER*NPROJ];    // B-perm [K=2048][N=256] (padded)
__device__ __half g_WBB  [DSTATE*DINNER];   // B-perm [K=64][N=2048]
__device__ __half g_WCB  [DSTATE*DINNER];   // B-perm [K=64][N=2048]
__device__ __half g_WoutB[DINNER*DMODEL];   // B-perm [K=2048][N=1024]

// ---------------- helpers ----------------------------------------------------
__device__ __forceinline__ void cp_async16(uint32_t saddr, const void* gptr) {
    asm volatile("cp.async.cg.shared.global [%0], [%1], 16;" :: "r"(saddr), "l"(gptr));
}
__device__ __forceinline__ void cp_commit() {
    asm volatile("cp.async.commit_group;");
}
template<int N>
__device__ __forceinline__ void cp_wait() {
    asm volatile("cp.async.wait_group %0;" :: "n"(N));
}
__device__ __forceinline__ void mma_f16(
    float& c0, float& c1, float& c2, float& c3,
    unsigned a0, unsigned a1, unsigned a2, unsigned a3,
    unsigned b0, unsigned b1)
{
    asm volatile(
        "mma.sync.aligned.m16n8k16.row.col.f32.f16.f16.f32 "
        "{%0,%1,%2,%3}, {%4,%5,%6,%7}, {%8,%9}, {%0,%1,%2,%3};"
        : "+f"(c0), "+f"(c1), "+f"(c2), "+f"(c3)
        : "r"(a0), "r"(a1), "r"(a2), "r"(a3), "r"(b0), "r"(b1));
}

// fragment-major (m16n8k16 fp16) index helpers -> index into half array.
// A block (m16 x k16) = 256 halfs. lane = (m%8)*4 + ((k%8)>>1);
// slot = ((m%16)>=8) + 2*((k%16)>=8); half-in-word = k&1.
__device__ __forceinline__ size_t permAh(int m, int k, int K16) {
    size_t block = (size_t)(m >> 4) * K16 + (k >> 4);
    int lane = (m & 7) * 4 + ((k >> 1) & 3);
    int slot = ((m >> 3) & 1) + 2 * ((k >> 3) & 1);
    return block * 256 + (lane * 4 + slot) * 2 + (k & 1);
}
// B block (n8 x k16) = 128 halfs. lane = (n%8)*4 + ((k%8)>>1); slot = (k%16)>=8.
__device__ __forceinline__ size_t permBh(int k, int n, int K16) {
    size_t block = (size_t)(n >> 3) * K16 + (k >> 4);
    int lane = (n & 7) * 4 + ((k >> 1) & 3);
    int slot = (k >> 3) & 1;
    return block * 128 + (lane * 2 + slot) * 2 + (k & 1);
}

// ---------------- operand prep kernels ---------------------------------------
__global__ void permA_h_kernel(__half* __restrict__ dst,
                               const float* __restrict__ src, int K)
{
    int idx = blockIdx.x * 256 + threadIdx.x;
    int m = idx / K, k = idx % K;
    dst[permAh(m, k, K >> 4)] = __float2half_rn(src[idx]);
}

__global__ void permB_h_kernel(__half* __restrict__ dst,
                               const float* __restrict__ src,
                               int K, int N, int ldsrc, int ncols)
{
    int idx = blockIdx.x * 256 + threadIdx.x;   // K*N total
    int k = idx / N, n = idx % N;
    float v = (n < ncols) ? src[(size_t)k * ldsrc + n] : 0.f;
    dst[permBh(k, n, K >> 4)] = __float2half_rn(v);
}

// ---------------- fp16 mma.sync GEMM, frag-major smem, 3-stage cp.async ------
// C[M,N] = A@B fp16 in / fp32 accum+out. CTA 128x128, BK=16, 8 warps (2m x 4n).
// MODE 0: generic; blockIdx.z selects (Ap,Bp,C0) vs (Ap2,Bp2,Cz) fused dual GEMM.
// MODE 1 (GEMM1): col<DINNER -> xi(C0) + xirP(P0, fp16 perm K16=128); else z(C1).
#define STG_BYTES 8192           // per stage: A 4KB + B 4KB

template<int MODE>
__global__ void __launch_bounds__(256) h16gemm(
    const __half* __restrict__ Ap, const __half* __restrict__ Bp,
    const __half* __restrict__ Ap2, const __half* __restrict__ Bp2,
    float* __restrict__ C0, float* __restrict__ C1, float* __restrict__ Cz,
    __half* __restrict__ P0, int ldc, int K)
{
    __shared__ __align__(16) char smbuf[3 * STG_BYTES];   // 24KB

    const int tid  = threadIdx.x;
    const int warp = tid >> 5;
    const int lane = tid & 31;
    const int lq   = lane & 3;
    const int lr   = lane >> 2;
    const int m0   = blockIdx.y * 128;
    const int n0   = blockIdx.x * 128;
    const int K16  = K >> 4;
    const int wmg  = (warp >> 2) * 4;   // warp m16-block base
    const int wng  = (warp & 3) * 4;    // warp n8-block base

    const bool alt = (MODE == 0) && (blockIdx.z == 1);
    const __half* Asel = alt ? Ap2 : Ap;
    const __half* Bsel = alt ? Bp2 : Bp;
    float* Csel = alt ? Cz : C0;

    const uint32_t sbase = (uint32_t)__cvta_generic_to_shared(smbuf);

    float acc[4][4][4];
#pragma unroll
    for (int i = 0; i < 4; i++)
#pragma unroll
        for (int j = 0; j < 4; j++)
#pragma unroll
            for (int c = 0; c < 4; c++) acc[i][j][c] = 0.f;

    // stage loader: K16-chunk i into stage s. A: 8 blocks x 512B; B: 16 x 256B.
    auto stage = [&](int i, int s) {
        cp_async16(sbase + s * STG_BYTES + tid * 16,
            Asel + ((size_t)((m0 >> 4) + (tid >> 5)) * K16 + i) * 256 + (tid & 31) * 8);
        cp_async16(sbase + s * STG_BYTES + 4096 + tid * 16,
            Bsel + ((size_t)((n0 >> 3) + (tid >> 4)) * K16 + i) * 128 + (tid & 15) * 8);
    };

    stage(0, 0); cp_commit();
    stage(1, 1); cp_commit();

    for (int i = 0; i < K16; i++) {
        if (i == K16 - 1) cp_wait<0>(); else cp_wait<1>();
        __syncthreads();
        if (i + 2 < K16) { stage(i + 2, (i + 2) % 3); cp_commit(); }

        const __half* sa = (const __half*)(smbuf + (i % 3) * STG_BYTES);
        const __half* sb = sa + 2048;

        uint4 af[4];
        uint2 bf[4];
#pragma unroll
        for (int mt = 0; mt < 4; mt++)
            af[mt] = *(const uint4*)(sa + (wmg + mt) * 256 + lane * 8);
#pragma unroll
        for (int nt = 0; nt < 4; nt++)
            bf[nt] = *(const uint2*)(sb + (wng + nt) * 128 + lane * 4);
#pragma unroll
        for (int mt = 0; mt < 4; mt++)
#pragma unroll
            for (int nt = 0; nt < 4; nt++)
                mma_f16(acc[mt][nt][0], acc[mt][nt][1], acc[mt][nt][2], acc[mt][nt][3],
                        af[mt].x, af[mt].y, af[mt].z, af[mt].w,
                        bf[nt].x, bf[nt].y);
    }

    // epilogue: c0=(row,col) c1=(row,col+1) c2/c3 at row+8
#pragma unroll
    for (int mt = 0; mt < 4; mt++) {
#pragma unroll
        for (int nt = 0; nt < 4; nt++) {
            int row = m0 + (warp >> 2) * 64 + mt * 16 + lr;
            int col = n0 + (warp & 3) * 32 + nt * 8 + lq * 2;
            float2 v0 = make_float2(acc[mt][nt][0], acc[mt][nt][1]);
            float2 v1 = make_float2(acc[mt][nt][2], acc[mt][nt][3]);
            if (MODE == 1) {
                if (col < DINNER) {
                    *(float2*)(C0 + (size_t)row * DINNER + col)       = v0;
                    *(float2*)(C0 + (size_t)(row + 8) * DINNER + col) = v1;
                    // fp16 perm: (col, col+1) are adjacent halfs of one word
                    *(__half2*)(P0 + permAh(row,     col, 128)) = __floats2half2_rn(v0.x, v0.y);
                    *(__half2*)(P0 + permAh(row + 8, col, 128)) = __floats2half2_rn(v1.x, v1.y);
                } else {
                    *(float2*)(C1 + (size_t)row * DINNER + col - DINNER)       = v0;
                    *(float2*)(C1 + (size_t)(row + 8) * DINNER + col - DINNER) = v1;
                }
            } else {
                *(float2*)(Csel + (size_t)row * ldc + col)       = v0;
                *(float2*)(Csel + (size_t)(row + 8) * ldc + col) = v1;
            }
        }
    }
}

// ---------------- proj epilogue: a / BrawP / CrawP from padded proj ----------
__global__ void __launch_bounds__(128) proj_epi_kernel(const float* __restrict__ A_log)
{
    int row = blockIdx.x;
    int tid = threadIdx.x;
    const float* pr = g_proj + (size_t)row * NPROJ;
    if (tid < 64)
        g_BrawP[permAh(row, tid, 4)] = __float2half_rn(pr[1 + tid]);
    else
        g_CrawP[permAh(row, tid - 64, 4)] = __float2half_rn(pr[65 + (tid - 64)]);
    if (tid == 0) {
        float x  = pr[0];
        float sp = fmaxf(x, 0.f) + log1pf(expf(-fabsf(x)));  // softplus
        g_a[row] = expf(-expf(A_log[0]) * sp);
    }
}

// ---------------- chunk products of a ---------------------------------------
__global__ void chunkprod_kernel()
{
    int i = blockIdx.x * blockDim.x + threadIdx.x;
    if (i < BATCH * NCHUNK) {
        float p = 1.f;
        int base = i * CHUNK;
        for (int t = 0; t < CHUNK; t++) p *= g_a[base + t];
        g_P[i] = p;
    }
}

// ---------------- pass 1: local chunk scan -> chunk-final h -----------------
__global__ void __launch_bounds__(256) scan1_kernel()
{
    __shared__ float a_sm[CHUNK];
    int d = blockIdx.x * 256 + threadIdx.x;
    int c = blockIdx.y, b = blockIdx.z;
    int mbase = b * SEQ + c * CHUNK;
    if (threadIdx.x < CHUNK) a_sm[threadIdx.x] = g_a[mbase + threadIdx.x];
    __syncthreads();

    float h = 0.f;
    size_t off = (size_t)mbase * DINNER + d;
#pragma unroll 4
    for (int t = 0; t < CHUNK; t++) {
        size_t idx = off + (size_t)t * DINNER;
        h = fmaf(a_sm[t], h, g_Bm[idx] * g_xi[idx]);
    }
    g_hfin[(size_t)(b * NCHUNK + c) * DINNER + d] = h;
}

// ---------------- pass 2: carry across chunks --------------------------------
__global__ void scan2_kernel()
{
    int gid = blockIdx.x * blockDim.x + threadIdx.x;
    int b = gid / DINNER, d = gid % DINNER;
    float carry = 0.f;
    for (int c = 0; c < NCHUNK; c++) {
        int i = b * NCHUNK + c;
        g_carry[(size_t)i * DINNER + d] = carry;
        carry = g_P[i] * carry + g_hfin[(size_t)i * DINNER + d];
    }
}

// ---------------- pass 3: scan + fused y = (C*h + D*xi)*silu(z) --------------
// writes fp16 y directly in A-perm layout (GEMM4 operand, K16=128)
__global__ void __launch_bounds__(256) scan3_kernel(const float* __restrict__ Dvec)
{
    __shared__ float a_sm[CHUNK];
    int d = blockIdx.x * 256 + threadIdx.x;
    int c = blockIdx.y, b = blockIdx.z;
    int mbase = b * SEQ + c * CHUNK;
    if (threadIdx.x < CHUNK) a_sm[threadIdx.x] = g_a[mbase + threadIdx.x];
    __syncthreads();

    float h  = g_carry[(size_t)(b * NCHUNK + c) * DINNER + d];
    float Dd = Dvec[d];
    size_t off = (size_t)mbase * DINNER + d;
#pragma unroll 2
    for (int t = 0; t < CHUNK; t++) {
        size_t idx = off + (size_t)t * DINNER;
        float xiv = g_xi[idx];
        h = fmaf(a_sm[t], h, g_Bm[idx] * xiv);
        float zv  = g_z[idx];
        float sil = zv / (1.f + expf(-zv));
        g_yP[permAh(mbase + t, d, 128)] =
            __float2half_rn((g_Cm[idx] * h + Dd * xiv) * sil);
    }
}

// ---------------- launch -----------------------------------------------------
extern "C" void kernel_launch(void* const* d_in, const int* in_sizes, int n_in,
                              void* d_out, int out_size)
{
    const float* x     = (const float*)d_in[0];
    const float* W_in  = (const float*)d_in[1];
    const float* W_xp  = (const float*)d_in[2];
    const float* W_B   = (const float*)d_in[3];
    const float* W_C   = (const float*)d_in[4];
    const float* W_out = (const float*)d_in[5];
    const float* Dv    = (const float*)d_in[6];
    const float* A_log = (const float*)d_in[7];
    float* out = (float*)d_out;

    float *p_xi, *p_z, *p_Bm, *p_Cm, *p_proj;
    __half *p_xAP, *p_xirP, *p_BrawP, *p_CrawP, *p_yP;
    __half *p_WinB, *p_WxpB, *p_WBB, *p_WCB, *p_WoutB;
    cudaGetSymbolAddress((void**)&p_xi,    g_xi);
    cudaGetSymbolAddress((void**)&p_z,     g_z);
    cudaGetSymbolAddress((void**)&p_Bm,    g_Bm);
    cudaGetSymbolAddress((void**)&p_Cm,    g_Cm);
    cudaGetSymbolAddress((void**)&p_proj,  g_proj);
    cudaGetSymbolAddress((void**)&p_xAP,   g_xAP);
    cudaGetSymbolAddress((void**)&p_xirP,  g_xirP);
    cudaGetSymbolAddress((void**)&p_BrawP, g_BrawP);
    cudaGetSymbolAddress((void**)&p_CrawP, g_CrawP);
    cudaGetSymbolAddress((void**)&p_yP,    g_yP);
    cudaGetSymbolAddress((void**)&p_WinB,  g_WinB);
    cudaGetSymbolAddress((void**)&p_WxpB,  g_WxpB);
    cudaGetSymbolAddress((void**)&p_WBB,   g_WBB);
    cudaGetSymbolAddress((void**)&p_WCB,   g_WCB);
    cudaGetSymbolAddress((void**)&p_WoutB, g_WoutB);

    // 0) operand prep (convert once to fp16 fragment-major layouts)
    permA_h_kernel<<<(MROWS * DMODEL) / 256, 256>>>(p_xAP, x, DMODEL);
    permB_h_kernel<<<(DMODEL * 2 * DINNER) / 256, 256>>>(
        p_WinB, W_in, DMODEL, 2 * DINNER, 2 * DINNER, 2 * DINNER);
    permB_h_kernel<<<(DINNER * NPROJ) / 256, 256>>>(
        p_WxpB, W_xp, DINNER, NPROJ, 129, 129);
    permB_h_kernel<<<(DSTATE * DINNER) / 256, 256>>>(
        p_WBB, W_B, DSTATE, DINNER, DINNER, DINNER);
    permB_h_kernel<<<(DSTATE * DINNER) / 256, 256>>>(
        p_WCB, W_C, DSTATE, DINNER, DINNER, DINNER);
    permB_h_kernel<<<(DINNER * DMODEL) / 256, 256>>>(
        p_WoutB, W_out, DINNER, DMODEL, DMODEL, DMODEL);

    // GEMM1: xz = x @ W_in -> xi | z (+ xir perm)   (8192 x 4096 x 1024)
    h16gemm<1><<<dim3((2 * DINNER) / 128, MROWS / 128), 256>>>(
        p_xAP, p_WinB, nullptr, nullptr, p_xi, p_z, nullptr, p_xirP, DINNER, DMODEL);

    // GEMM2: proj = xi_r @ W_xp_pad   (8192 x 256 x 2048)
    h16gemm<0><<<dim3(NPROJ / 128, MROWS / 128), 256>>>(
        p_xirP, p_WxpB, nullptr, nullptr, p_proj, nullptr, nullptr, nullptr,
        NPROJ, DINNER);
    proj_epi_kernel<<<MROWS, 128>>>(A_log);
    chunkprod_kernel<<<1, 64>>>();

    // GEMM3 fused pair (blockIdx.z): z=0: Bm = Braw@W_B ; z=1: Cm = Craw@W_C
    h16gemm<0><<<dim3(DINNER / 128, MROWS / 128, 2), 256>>>(
        p_BrawP, p_WBB, p_CrawP, p_WCB, p_Bm, nullptr, p_Cm, nullptr,
        DINNER, DSTATE);

    // chunked scan
    scan1_kernel<<<dim3(DINNER / 256, NCHUNK, BATCH), 256>>>();
    scan2_kernel<<<32, 256>>>();
    scan3_kernel<<<dim3(DINNER / 256, NCHUNK, BATCH), 256>>>(Dv);

    // GEMM4: out = y @ W_out   (8192 x 1024 x 2048)
    h16gemm<0><<<dim3(DMODEL / 128, MROWS / 128), 256>>>(
        p_yP, p_WoutB, nullptr, nullptr, out, nullptr, nullptr, nullptr,
        DMODEL, DINNER);
}